// round 1
// baseline (speedup 1.0000x reference)
#include <cuda_runtime.h>

// eTofts DCE-MRI forward model.
// Inputs (metadata order): param [B,3] f32, T10 [B,1] f32, cp [B,T] f32.
// Output: [B,T] f32.
//
// Per row:
//   ktrans = clamp(p0*0.2, 1e-5, 0.2); vp = clamp(p1*0.1, 5e-4, 0.1);
//   ve = clamp(p2*0.6, 0.04, 0.6); decay = exp(-(ktrans/ve)*DELTT)
//   IIR: c[t] = c[t-1]*decay + cp[t]*DELTT ; ce = ktrans*c
//   ct = vp*cp + ce ; R1 = 1/T10 + 4.5*ct
//   E = exp(-TR*R1) ; out = 20*sinA*(1-E)/(1-cosA*E)
//
// Strategy: 64-row tile per CTA staged through shared memory so all global
// traffic is coalesced float4; odd smem stride (113) keeps both the
// scatter-write and the per-thread row scan bank-conflict-free. All math
// folded into FMAs + one EX2 + one RCP per element.

#define TT     112
#define ROWS   64
#define STRIDE 113   // odd -> conflict-free column & row access
#define N4     (ROWS * TT / 4)

__device__ __forceinline__ float ex2f(float x) {
    float y;
    asm("ex2.approx.ftz.f32 %0, %1;" : "=f"(y) : "f"(x));
    return y;
}
__device__ __forceinline__ float rcpf(float x) {
    float y;
    asm("rcp.approx.ftz.f32 %0, %1;" : "=f"(y) : "f"(x));
    return y;
}

__global__ __launch_bounds__(ROWS) void etofts_kernel(
    const float* __restrict__ param,
    const float* __restrict__ T10,
    const float* __restrict__ cp,
    float* __restrict__ out)
{
    __shared__ float tile[ROWS * STRIDE];
    const int tid  = threadIdx.x;
    const int row0 = blockIdx.x * ROWS;

    // ---- coalesced float4 load of the cp tile into smem (transposed layout) ----
    const float4* cp4 = (const float4*)(cp + (size_t)row0 * TT);
    #pragma unroll 7
    for (int j = tid; j < N4; j += ROWS) {
        float4 v = cp4[j];
        int r = j / (TT / 4);
        int c = (j - r * (TT / 4)) * 4;
        float* d = &tile[r * STRIDE + c];
        d[0] = v.x; d[1] = v.y; d[2] = v.z; d[3] = v.w;
    }
    __syncthreads();

    // ---- per-row constants ----
    const int row = row0 + tid;
    const float p0  = param[row * 3 + 0];
    const float p1  = param[row * 3 + 1];
    const float p2  = param[row * 3 + 2];
    const float t10 = T10[row];

    const float ktrans = fminf(fmaxf(p0 * 0.2f, 1e-5f),   0.2f);
    const float vp     = fminf(fmaxf(p1 * 0.1f, 0.0005f), 0.1f);
    const float ve     = fminf(fmaxf(p2 * 0.6f, 0.04f),   0.6f);

    const float DELTT = 0.075f;                 // 4.5/60
    const float LOG2E = 1.4426950408889634f;
    const float TR    = 0.005f;
    const float SINA  = 0.25881904510252074f;   // sin(15 deg)
    const float COSA  = 0.9659258262890683f;    // cos(15 deg)

    const float decay = ex2f(-(ktrans / ve) * (DELTT * LOG2E));
    const float c1    = -(TR * 4.5f * LOG2E);   // log2-domain coeff of ct
    const float c0    = -(TR * LOG2E) * rcpf(t10);
    const float b_cp  = c1 * vp;                // coeff of cp[t]
    const float b_u   = c1 * ktrans * DELTT;    // coeff of scaled IIR state u
    const float numA  = 20.0f * SINA;

    // ---- sequential scan over T, compute in place ----
    float* myrow = &tile[tid * STRIDE];
    float u = 0.0f;
    #pragma unroll 8
    for (int t = 0; t < TT; t++) {
        float cpt = myrow[t];
        u = fmaf(u, decay, cpt);                          // u = c/DELTT recurrence
        float arg = fmaf(b_cp, cpt, fmaf(b_u, u, c0));    // log2(E)
        float E   = ex2f(arg);
        float num = fmaf(E, -numA, numA);                 // 20*sinA*(1-E)
        float den = fmaf(E, -COSA, 1.0f);                 // 1 - cosA*E
        myrow[t]  = num * rcpf(den);
    }
    __syncthreads();

    // ---- coalesced float4 store ----
    float4* out4 = (float4*)(out + (size_t)row0 * TT);
    #pragma unroll 7
    for (int j = tid; j < N4; j += ROWS) {
        int r = j / (TT / 4);
        int c = (j - r * (TT / 4)) * 4;
        const float* s = &tile[r * STRIDE + c];
        out4[j] = make_float4(s[0], s[1], s[2], s[3]);
    }
}

extern "C" void kernel_launch(void* const* d_in, const int* in_sizes, int n_in,
                              void* d_out, int out_size)
{
    const float* param = (const float*)d_in[0];
    const float* T10   = (const float*)d_in[1];
    const float* cp    = (const float*)d_in[2];
    float*       out   = (float*)d_out;

    const int B = in_sizes[1];          // T10 has B elements
    etofts_kernel<<<B / ROWS, ROWS>>>(param, T10, cp, out);
}